// round 3
// baseline (speedup 1.0000x reference)
#include <cuda_runtime.h>
#include <math.h>

#define BN 32     // B*C images
#define HH 256
#define WW 256
#define TILE 32   // output rows per block
#define HALO 16   // shared halo rows each side; covers d <= 16 exactly
#define SROWS (TILE + 2*HALO)   // 64
#define FG_INF 1e6f
#define BIGF   3.0e38f          // padding: r2 + BIGF never wins, no overflow

// exact per-pixel row distance recompute from x (cold path only)
__device__ float row_g(const float* __restrict__ xrow, int j) {
    int dl = 1 << 30, dr = 1 << 30;
    for (int t = j; t >= 0; --t)  if (xrow[t] == 0.0f) { dl = j - t; break; }
    for (int t = j; t < WW; ++t)  if (xrow[t] == 0.0f) { dr = t - j; break; }
    int d = min(dl, dr);
    if (d >= (1 << 30))
        return FG_INF + fminf((float)(j + 1), (float)(WW - j));
    return (float)d;
}

__global__ void __launch_bounds__(1024, 2)
edt_fused(const float* __restrict__ x, float* __restrict__ out) {
    __shared__ float g2s[SROWS][WW];   // 64 KB; sign bit of center = NaN flag

    const int n  = blockIdx.y;                 // image
    const int i0 = blockIdx.x * TILE;          // first output row
    const int rowbase = i0 - HALO;             // global row of shared row 0
    const int lane = threadIdx.x & 31;
    const int wrp  = threadIdx.x >> 5;         // 0..31

    // ---------------- Phase 1: row distances (warp-per-row) ----------------
    #pragma unroll
    for (int pass = 0; pass < 2; ++pass) {
        const int lr = wrp + pass * 32;        // local shared row 0..63
        const int gr = rowbase + lr;           // global row
        if (gr < 0 || gr >= HH) {
            #pragma unroll
            for (int k = 0; k < 8; ++k) g2s[lr][lane + 32 * k] = BIGF;
            continue;
        }
        const float* __restrict__ xr = x + (n * HH + gr) * WW;
        float xv[8];
        unsigned m[8];
        #pragma unroll
        for (int k = 0; k < 8; ++k) {
            xv[k] = xr[lane + 32 * k];
            m[k]  = __ballot_sync(0xFFFFFFFFu, xv[k] == 0.0f);  // NaN -> fg
        }
        unsigned long long w64[4];
        #pragma unroll
        for (int q = 0; q < 4; ++q)
            w64[q] = (unsigned long long)m[2 * q] |
                     ((unsigned long long)m[2 * q + 1] << 32);

        #pragma unroll
        for (int k = 0; k < 8; ++k) {
            const int j = lane + 32 * k;
            float g;
            if (xv[k] == 0.0f) {
                g = 0.0f;
            } else {
                const int q = j >> 6, b = j & 63;
                // nearest bg to the right (bit pos > j)
                int dr = 1 << 30;
                unsigned long long hi =
                    (b == 63) ? 0ull : (w64[q] & (~0ull << (b + 1)));
                if (hi) dr = __ffsll((long long)hi) - 1 - b;
                else {
                    #pragma unroll
                    for (int t = 1; t < 4; ++t) {
                        int tq = q + t;
                        if (tq < 4 && w64[tq]) {
                            dr = 64 * t + __ffsll((long long)w64[tq]) - 1 - b;
                            break;
                        }
                    }
                }
                // nearest bg to the left (bit pos < j)
                int dl = 1 << 30;
                unsigned long long lo =
                    (b == 0) ? 0ull : (w64[q] & ((1ull << b) - 1ull));
                if (lo) dl = b - (63 - __clzll((long long)lo));
                else {
                    #pragma unroll
                    for (int t = 1; t < 4; ++t) {
                        int tq = q - t;
                        if (tq >= 0 && w64[tq]) {
                            dl = 64 * t + b - (63 - __clzll((long long)w64[tq]));
                            break;
                        }
                    }
                }
                int d = min(dl, dr);
                g = (d >= (1 << 30))
                    ? FG_INF + fminf((float)(j + 1), (float)(WW - j))
                    : (float)d;
            }
            float s2 = g * g;
            if (isnan(xv[k])) s2 = -s2;   // fg => g>=1, sign bit is free
            g2s[lr][j] = s2;
        }
    }
    __syncthreads();

    // ---------------- Phase 2: column lower-envelope ----------------
    // D2[i,j] = min_k (i-k)^2 + g2[k,j]; exact early termination.
    const int j   = threadIdx.x & (WW - 1);
    const int ty  = threadIdx.x >> 8;      // 0..3
    const int lo0 = ty * 8;                // first local output row (of 8)

    float v[16];                           // shared rows H+lo0-4 .. H+lo0+11
    #pragma unroll
    for (int t = 0; t < 16; ++t)
        v[t] = g2s[HALO + lo0 - 4 + t][j];

    #pragma unroll
    for (int p = 0; p < 8; ++p) {
        const int c = 4 + p;
        const float center = v[c];
        const bool nanp = signbit(center);
        float best = fabsf(center);
        #pragma unroll
        for (int r = 1; r <= 4; ++r) {
            const float r2 = (float)(r * r);
            best = fminf(best, r2 + fabsf(v[c - r]));
            best = fminf(best, r2 + fabsf(v[c + r]));
        }
        if (25.0f < best) {
            const int s = HALO + lo0 + p;          // shared row of this pixel
            // shared tail: r = 5..HALO always in shared bounds (BIGF-padded)
            for (int r = 5; r <= HALO; ++r) {
                const float r2 = (float)(r * r);
                if (r2 >= best) break;
                best = fminf(best, r2 + fabsf(g2s[s - r][j]));
                best = fminf(best, r2 + fabsf(g2s[s + r][j]));
            }
            // exact global fallback (never taken for this data distribution)
            if ((float)(HALO * HALO) < best) {
                const int i = i0 + lo0 + p;
                for (int r = HALO + 1; r < HH; ++r) {
                    const float r2 = (float)(r * r);
                    if (r2 >= best) break;
                    const int up = i - r, dn = i + r;
                    if (up >= 0) {
                        float g = row_g(x + (n * HH + up) * WW, j);
                        best = fminf(best, r2 + g * g);
                    }
                    if (dn < HH) {
                        float g = row_g(x + (n * HH + dn) * WW, j);
                        best = fminf(best, r2 + g * g);
                    }
                }
            }
        }
        const float d = sqrtf(best);
        out[(n * HH + i0 + lo0 + p) * WW + j] =
            nanp ? __int_as_float(0x7FC00000) : d;
    }
}

extern "C" void kernel_launch(void* const* d_in, const int* in_sizes, int n_in,
                              void* d_out, int out_size) {
    const float* x = (const float*)d_in[0];
    float* out = (float*)d_out;
    edt_fused<<<dim3(HH / TILE, BN), 1024>>>(x, out);
}

// round 4
// speedup vs baseline: 1.2424x; 1.2424x over previous
#include <cuda_runtime.h>
#include <math.h>

#define BN 32     // B*C images
#define HH 256
#define WW 256
#define TILE 32   // output rows per block
#define HALO 8    // shared halo rows each side; covers column d <= 8 exactly
#define SROWS (TILE + 2*HALO)   // 48
#define FG_INF 1e6f
#define BIGF   3.0e38f          // padding: r2 + BIGF never wins, no overflow

// exact per-pixel row distance recompute from x (cold path, never hot)
__device__ __forceinline__ float row_g_global(const float* __restrict__ xrow, int j) {
    if (xrow[j] == 0.0f) return 0.0f;
    int dl = 1 << 30, dr = 1 << 30;
    for (int t = j - 1; t >= 0; --t) if (xrow[t] == 0.0f) { dl = j - t; break; }
    for (int t = j + 1; t < WW; ++t) if (xrow[t] == 0.0f) { dr = t - j; break; }
    int d = min(dl, dr);
    if (d >= (1 << 30)) return FG_INF + fminf((float)(j + 1), (float)(WW - j));
    return (float)d;
}

__global__ void __launch_bounds__(512, 2)
edt_fused(const float* __restrict__ x, float* __restrict__ out) {
    __shared__ float g2s[SROWS][WW];   // 48 KB; sign bit = "input was NaN"

    const int n  = blockIdx.y;                 // image
    const int i0 = blockIdx.x * TILE;          // first output row
    const int rowbase = i0 - HALO;             // global row of shared row 0
    const int lane = threadIdx.x & 31;
    const int wrp  = threadIdx.x >> 5;         // 0..15

    // ------------- Phase 1: row distances (warp-per-row, branch-free) -------------
    #pragma unroll
    for (int pass = 0; pass < 3; ++pass) {
        const int lr = wrp + pass * 16;        // local shared row 0..47
        const int gr = rowbase + lr;           // global row
        if (gr < 0 || gr >= HH) {
            #pragma unroll
            for (int k = 0; k < 8; ++k) g2s[lr][lane + 32 * k] = BIGF;
            continue;
        }
        const float* __restrict__ xr = x + (n * HH + gr) * WW;

        unsigned mm[10];                       // bg mask words, zero-padded ends
        unsigned nn[8];                        // NaN mask words
        mm[0] = 0u; mm[9] = 0u;
        #pragma unroll
        for (int k = 0; k < 8; ++k) {
            const float xv = xr[lane + 32 * k];
            mm[k + 1] = __ballot_sync(0xFFFFFFFFu, xv == 0.0f);  // NaN -> fg
            nn[k]     = __ballot_sync(0xFFFFFFFFu, isnan(xv));
        }

        const int b = lane;
        #pragma unroll
        for (int k = 0; k < 8; ++k) {
            const int j = b + 32 * k;
            float g;
            if ((mm[k + 1] >> b) & 1u) {
                g = 0.0f;
            } else {
                // right window: distances 1 .. 63-b ; left window: 1 .. 32+b
                const unsigned long long R =
                    (((unsigned long long)mm[k + 1]) >> (b + 1)) |
                    (((unsigned long long)mm[k + 2]) << (31 - b));
                const unsigned long long L =
                    (((unsigned long long)mm[k + 1]) << (63 - b)) |
                    (((unsigned long long)mm[k    ]) << (31 - b));
                const int dr = R ? __ffsll((long long)R) : (1 << 30);
                const int dl = L ? __clzll((long long)L) : (1 << 30);
                int d = min(dl, dr);
                if (d > 32) {
                    // exact cold fallback: scan all mask words
                    d = 1 << 30;
                    #pragma unroll
                    for (int q = 0; q < 8; ++q) {
                        unsigned w = mm[q + 1];
                        while (w) {
                            const int t = __ffs(w) - 1;
                            w &= w - 1;
                            d = min(d, abs(32 * q + t - j));
                        }
                    }
                }
                g = (d >= (1 << 30))
                    ? FG_INF + fminf((float)(j + 1), (float)(WW - j))
                    : (float)d;
            }
            float s2 = g * g;
            if ((nn[k] >> b) & 1u) s2 = -s2;   // fg => g>=1, sign bit free
            g2s[lr][j] = s2;
        }
    }
    __syncthreads();

    // ------------- Phase 2: column lower-envelope (exact early exit) -------------
    const int j    = threadIdx.x & (WW - 1);
    const int half = threadIdx.x >> 8;         // 0..1

    #pragma unroll
    for (int sub = 0; sub < 2; ++sub) {
        const int lo0 = half * 16 + sub * 8;   // first of 8 local output rows
        float v[16];                           // shared rows HALO+lo0-4 .. +11
        #pragma unroll
        for (int t = 0; t < 16; ++t)
            v[t] = g2s[HALO + lo0 - 4 + t][j];

        #pragma unroll
        for (int p = 0; p < 8; ++p) {
            const int c = 4 + p;
            const float center = v[c];
            const bool nanp = signbit(center);
            float best = fabsf(center);
            #pragma unroll
            for (int r = 1; r <= 4; ++r) {
                const float r2 = (float)(r * r);
                best = fminf(best, r2 + fabsf(v[c - r]));
                best = fminf(best, r2 + fabsf(v[c + r]));
            }
            if (25.0f < best) {
                const int s = HALO + lo0 + p;  // this pixel's shared row
                #pragma unroll
                for (int r = 5; r <= HALO; ++r) {
                    const float r2 = (float)(r * r);
                    if (r2 >= best) break;
                    best = fminf(best, r2 + fabsf(g2s[s - r][j]));
                    best = fminf(best, r2 + fabsf(g2s[s + r][j]));
                }
                // exact global fallback (never taken for this distribution)
                if ((float)(HALO * HALO) < best) {
                    const int i = i0 + lo0 + p;
                    for (int r = HALO + 1; r < HH; ++r) {
                        const float r2 = (float)(r * r);
                        if (r2 >= best) break;
                        const int up = i - r, dn = i + r;
                        if (up >= 0) {
                            const float g = row_g_global(x + (n * HH + up) * WW, j);
                            best = fminf(best, r2 + g * g);
                        }
                        if (dn < HH) {
                            const float g = row_g_global(x + (n * HH + dn) * WW, j);
                            best = fminf(best, r2 + g * g);
                        }
                    }
                }
            }
            const float d = sqrtf(best);
            out[(n * HH + i0 + lo0 + p) * WW + j] =
                nanp ? __int_as_float(0x7FC00000) : d;
        }
    }
}

extern "C" void kernel_launch(void* const* d_in, const int* in_sizes, int n_in,
                              void* d_out, int out_size) {
    const float* x = (const float*)d_in[0];
    float* out = (float*)d_out;
    edt_fused<<<dim3(HH / TILE, BN), 512>>>(x, out);
}

// round 5
// speedup vs baseline: 1.3928x; 1.1210x over previous
#include <cuda_runtime.h>
#include <math.h>

#define BN 32     // B*C images
#define HH 256
#define WW 256
#define TILE 16   // output rows per block
#define HALO 8    // shared halo rows each side; covers column d <= 8 exactly
#define SROWS (TILE + 2*HALO)   // 32
#define FG_INF 1e6f
#define BIGF   3.0e38f          // padding: r2 + BIGF never wins, no overflow

// exact per-pixel row distance recompute from x (cold path, never hot)
__device__ __forceinline__ float row_g_global(const float* __restrict__ xrow, int j) {
    if (xrow[j] == 0.0f) return 0.0f;
    int dl = 1 << 30, dr = 1 << 30;
    for (int t = j - 1; t >= 0; --t) if (xrow[t] == 0.0f) { dl = j - t; break; }
    for (int t = j + 1; t < WW; ++t) if (xrow[t] == 0.0f) { dr = t - j; break; }
    int d = min(dl, dr);
    if (d >= (1 << 30)) return FG_INF + fminf((float)(j + 1), (float)(WW - j));
    return (float)d;
}

__global__ void __launch_bounds__(512, 3)
edt_fused(const float* __restrict__ x, float* __restrict__ out) {
    __shared__ float g2s[SROWS][WW];   // 32 KB; sign bit = "input was NaN"

    const int n  = blockIdx.y;                 // image
    const int i0 = blockIdx.x * TILE;          // first output row
    const int rowbase = i0 - HALO;             // global row of shared row 0
    const int b    = threadIdx.x & 31;         // lane
    const int wrp  = threadIdx.x >> 5;         // 0..15

    // ------- Phase 1: row distances (warp-per-row, funnel-shift search) -------
    #pragma unroll
    for (int pass = 0; pass < 2; ++pass) {
        const int lr = wrp + pass * 16;        // local shared row 0..31
        const int gr = rowbase + lr;           // global row
        if (gr < 0 || gr >= HH) {
            #pragma unroll
            for (int k = 0; k < 8; ++k) g2s[lr][b + 32 * k] = BIGF;
            continue;
        }
        const float* __restrict__ xr = x + (n * HH + gr) * WW;

        float xv[8];
        unsigned mm[10];                       // bg mask words, zero-padded ends
        mm[0] = 0u; mm[9] = 0u;
        #pragma unroll
        for (int k = 0; k < 8; ++k) {
            xv[k] = xr[b + 32 * k];
            mm[k + 1] = __ballot_sync(0xFFFFFFFFu, xv[k] == 0.0f);  // NaN -> fg
        }

        #pragma unroll
        for (int k = 0; k < 8; ++k) {
            const int j = b + 32 * k;
            const float xvk = xv[k];
            float s2;
            if (xvk == 0.0f) {
                s2 = 0.0f;
            } else {
                // 32-bit windows on each side, one funnel shift each:
                // R bit t  = pixel j+1+t ;  L bit (31-t) = pixel j-1-t
                const unsigned R = __funnelshift_rc(mm[k + 1], mm[k + 2], b + 1);
                const unsigned L = __funnelshift_lc(mm[k], mm[k + 1], 32 - b);
                const int dr = R ? __ffs(R) : 1000;
                const int dl = L ? (__clz(L) + 1) : 1000;
                int d = min(dr, dl);
                if (d < 1000) {
                    s2 = (float)(d * d);
                } else {
                    // cold exact fallback: scan every mask word
                    int db = 1 << 30;
                    #pragma unroll
                    for (int q = 1; q <= 8; ++q) {
                        unsigned w = mm[q];
                        while (w) {
                            const int t = __ffs(w) - 1;
                            w &= w - 1;
                            db = min(db, abs(32 * (q - 1) + t - j));
                        }
                    }
                    if (db >= (1 << 30)) {
                        const float gi =
                            FG_INF + fminf((float)(j + 1), (float)(WW - j));
                        s2 = gi * gi;
                    } else {
                        s2 = (float)(db * db);
                    }
                }
                if (isnan(xvk)) s2 = -s2;   // fg => g>=1, sign bit free
            }
            g2s[lr][j] = s2;
        }
    }
    __syncthreads();

    // ------- Phase 2: column lower-envelope (exact early exit) -------
    const int j   = threadIdx.x & (WW - 1);
    const int lo0 = (threadIdx.x >> 8) * 8;    // first of 8 local output rows

    float v[16];                               // shared rows HALO+lo0-4 .. +11
    #pragma unroll
    for (int t = 0; t < 16; ++t)
        v[t] = g2s[HALO + lo0 - 4 + t][j];

    #pragma unroll
    for (int p = 0; p < 8; ++p) {
        const int c = 4 + p;
        const float center = v[c];
        const bool nanp = signbit(center);
        float best = fabsf(center);
        #pragma unroll
        for (int r = 1; r <= 4; ++r) {
            const float r2 = (float)(r * r);
            best = fminf(best, r2 + fabsf(v[c - r]));
            best = fminf(best, r2 + fabsf(v[c + r]));
        }
        if (25.0f < best) {
            const int s = HALO + lo0 + p;      // this pixel's shared row
            #pragma unroll
            for (int r = 5; r <= HALO; ++r) {
                const float r2 = (float)(r * r);
                if (r2 >= best) break;
                best = fminf(best, r2 + fabsf(g2s[s - r][j]));
                best = fminf(best, r2 + fabsf(g2s[s + r][j]));
            }
            // exact global fallback (never taken for this distribution)
            if ((float)(HALO * HALO) < best) {
                const int i = i0 + lo0 + p;
                for (int r = HALO + 1; r < HH; ++r) {
                    const float r2 = (float)(r * r);
                    if (r2 >= best) break;
                    const int up = i - r, dn = i + r;
                    if (up >= 0) {
                        const float g = row_g_global(x + (n * HH + up) * WW, j);
                        best = fminf(best, r2 + g * g);
                    }
                    if (dn < HH) {
                        const float g = row_g_global(x + (n * HH + dn) * WW, j);
                        best = fminf(best, r2 + g * g);
                    }
                }
            }
        }
        const float d = sqrtf(best);
        out[(n * HH + i0 + lo0 + p) * WW + j] =
            nanp ? __int_as_float(0x7FC00000) : d;
    }
}

extern "C" void kernel_launch(void* const* d_in, const int* in_sizes, int n_in,
                              void* d_out, int out_size) {
    const float* x = (const float*)d_in[0];
    float* out = (float*)d_out;
    edt_fused<<<dim3(HH / TILE, BN), 512>>>(x, out);
}